// round 1
// baseline (speedup 1.0000x reference)
#include <cuda_runtime.h>
#include <cuda_bf16.h>

#define TT   48000
#define NCH  512
#define NTHR 160          // threads per block (5 warps)
#define LCH  300          // samples per thread: 160 * 300 = 48000, divisible by 4

__global__ __launch_bounds__(NTHR, 8) void biquad_kernel(
    const float* __restrict__ x,
    const float* __restrict__ b0v, const float* __restrict__ b1v,
    const float* __restrict__ b2v, const float* __restrict__ a1v,
    const float* __restrict__ a2v, float* __restrict__ y)
{
    __shared__ float sE1[NTHR], sE2[NTHR];   // per-chunk end states (zero-init)
    __shared__ float sS1[NTHR], sS2[NTHR];   // per-chunk true start states

    const int ch  = blockIdx.x;
    const int tid = threadIdx.x;

    const float B0 = b0v[ch], B1 = b1v[ch], B2 = b2v[ch];
    const float A1 = a1v[ch], A2 = a2v[ch];

    const float4* __restrict__ xc =
        (const float4*)(x + (size_t)ch * TT + (size_t)tid * LCH);

    // ---------------- Pass 1: run chunk from zero state, reference-form math ----
    float z1 = 0.f, z2 = 0.f;
    #pragma unroll 5
    for (int k = 0; k < LCH / 4; ++k) {
        float4 v = __ldg(xc + k);
        {
            float yn = fmaf(B0, v.x, z1);
            z1 = fmaf(B1, v.x, fmaf(-A1, yn, z2));
            z2 = fmaf(B2, v.x, -A2 * yn);
        }
        {
            float yn = fmaf(B0, v.y, z1);
            z1 = fmaf(B1, v.y, fmaf(-A1, yn, z2));
            z2 = fmaf(B2, v.y, -A2 * yn);
        }
        {
            float yn = fmaf(B0, v.z, z1);
            z1 = fmaf(B1, v.z, fmaf(-A1, yn, z2));
            z2 = fmaf(B2, v.z, -A2 * yn);
        }
        {
            float yn = fmaf(B0, v.w, z1);
            z1 = fmaf(B1, v.w, fmaf(-A1, yn, z2));
            z2 = fmaf(B2, v.w, -A2 * yn);
        }
    }
    sE1[tid] = z1;
    sE2[tid] = z2;
    __syncthreads();

    // ---------------- Block-serial scan of chunk states (thread 0) --------------
    // State transition per sample: s' = M s + c,  M = [[-A1, 1], [-A2, 0]].
    // Chunk-to-chunk: s_i = M^LCH * s_{i-1} + e_i.
    if (tid == 0) {
        // r = M^LCH via square-and-multiply (powers of one matrix commute)
        float m00 = -A1, m01 = 1.f, m10 = -A2, m11 = 0.f;
        float r00 = 1.f, r01 = 0.f, r10 = 0.f, r11 = 1.f;
        int e = LCH;
        while (e) {
            if (e & 1) {
                float t00 = r00 * m00 + r01 * m10;
                float t01 = r00 * m01 + r01 * m11;
                float t10 = r10 * m00 + r11 * m10;
                float t11 = r10 * m01 + r11 * m11;
                r00 = t00; r01 = t01; r10 = t10; r11 = t11;
            }
            e >>= 1;
            if (e) {
                float t00 = m00 * m00 + m01 * m10;
                float t01 = m00 * m01 + m01 * m11;
                float t10 = m10 * m00 + m11 * m10;
                float t11 = m10 * m01 + m11 * m11;
                m00 = t00; m01 = t01; m10 = t10; m11 = t11;
            }
        }
        float s1 = 0.f, s2 = 0.f;
        #pragma unroll 4
        for (int i = 0; i < NTHR; ++i) {
            sS1[i] = s1;
            sS2[i] = s2;
            float n1 = fmaf(r00, s1, fmaf(r01, s2, sE1[i]));
            float n2 = fmaf(r10, s1, fmaf(r11, s2, sE2[i]));
            s1 = n1; s2 = n2;
        }
    }
    __syncthreads();

    // ---------------- Pass 2: re-run chunk from true start state, write y -------
    z1 = sS1[tid];
    z2 = sS2[tid];
    float4* __restrict__ yc = (float4*)(y + (size_t)ch * TT + (size_t)tid * LCH);

    #pragma unroll 5
    for (int k = 0; k < LCH / 4; ++k) {
        float4 v = __ldg(xc + k);
        float4 o;
        {
            o.x = fmaf(B0, v.x, z1);
            z1 = fmaf(B1, v.x, fmaf(-A1, o.x, z2));
            z2 = fmaf(B2, v.x, -A2 * o.x);
        }
        {
            o.y = fmaf(B0, v.y, z1);
            z1 = fmaf(B1, v.y, fmaf(-A1, o.y, z2));
            z2 = fmaf(B2, v.y, -A2 * o.y);
        }
        {
            o.z = fmaf(B0, v.z, z1);
            z1 = fmaf(B1, v.z, fmaf(-A1, o.z, z2));
            z2 = fmaf(B2, v.z, -A2 * o.z);
        }
        {
            o.w = fmaf(B0, v.w, z1);
            z1 = fmaf(B1, v.w, fmaf(-A1, o.w, z2));
            z2 = fmaf(B2, v.w, -A2 * o.w);
        }
        yc[k] = o;
    }
}

extern "C" void kernel_launch(void* const* d_in, const int* in_sizes, int n_in,
                              void* d_out, int out_size)
{
    const float* x  = (const float*)d_in[0];
    const float* b0 = (const float*)d_in[1];
    const float* b1 = (const float*)d_in[2];
    const float* b2 = (const float*)d_in[3];
    const float* a1 = (const float*)d_in[4];
    const float* a2 = (const float*)d_in[5];
    float* y = (float*)d_out;

    biquad_kernel<<<NCH, NTHR>>>(x, b0, b1, b2, a1, a2, y);
}

// round 2
// speedup vs baseline: 2.1098x; 2.1098x over previous
#include <cuda_runtime.h>
#include <cuda_bf16.h>

#define TT    48000
#define NCH   512
#define NTHR  320                 // 10 warps
#define NW    (NTHR / 32)         // 10
#define LCH   25                  // samples per thread per tile (odd stride -> conflict-free LDS)
#define TILE  (NTHR * LCH)        // 8000 samples per tile
#define NTILE (TT / TILE)         // 6 tiles per channel

// 2x2 matrix multiply: O = A * B
#define MM(o00,o01,o10,o11, a00,a01,a10,a11, b00,b01,b10,b11) do { \
    float t00 = a00*b00 + a01*b10; \
    float t01 = a00*b01 + a01*b11; \
    float t10 = a10*b00 + a11*b10; \
    float t11 = a10*b01 + a11*b11; \
    o00=t00; o01=t01; o10=t10; o11=t11; } while(0)

__global__ __launch_bounds__(NTHR, 4) void biquad_kernel(
    const float* __restrict__ x,
    const float* __restrict__ b0v, const float* __restrict__ b1v,
    const float* __restrict__ b2v, const float* __restrict__ a1v,
    const float* __restrict__ a2v, float* __restrict__ y)
{
    __shared__ __align__(16) float xs[TILE];
    __shared__ float sT1[NW], sT2[NW];   // per-warp scan totals
    __shared__ float sC1[NW], sC2[NW];   // state entering each warp's first chunk

    const int ch   = blockIdx.x;
    const int tid  = threadIdx.x;
    const int lane = tid & 31;
    const int wrp  = tid >> 5;

    const float B0 = b0v[ch], B1 = b1v[ch], B2 = b2v[ch];
    const float A1 = a1v[ch], A2 = a2v[ch];
    const float nA1 = -A1, nA2 = -A2;

    // Per-sample state transition s' = M s + c(x), M = [[-A1, 1], [-A2, 0]].
    // R = M^LCH via square-and-multiply.
    float m00 = nA1, m01 = 1.f, m10 = nA2, m11 = 0.f;
    float r00 = 1.f, r01 = 0.f, r10 = 0.f, r11 = 1.f;
    {
        int e = LCH;
        while (e) {
            if (e & 1) { MM(r00,r01,r10,r11, r00,r01,r10,r11, m00,m01,m10,m11); }
            e >>= 1;
            if (e) { MM(m00,m01,m10,m11, m00,m01,m10,m11, m00,m01,m10,m11); }
        }
    }

    // P[k] = R^(2^k), k = 0..4 ; W = R^32
    float P00[5], P01[5], P10[5], P11[5];
    P00[0] = r00; P01[0] = r01; P10[0] = r10; P11[0] = r11;
    #pragma unroll
    for (int k = 1; k < 5; ++k) {
        MM(P00[k],P01[k],P10[k],P11[k],
           P00[k-1],P01[k-1],P10[k-1],P11[k-1],
           P00[k-1],P01[k-1],P10[k-1],P11[k-1]);
    }
    float W00, W01, W10, W11;   // R^32
    MM(W00,W01,W10,W11, P00[4],P01[4],P10[4],P11[4], P00[4],P01[4],P10[4],P11[4]);

    // Q = R^lane (product of selected P[k]; powers of one matrix commute)
    float q00 = 1.f, q01 = 0.f, q10 = 0.f, q11 = 1.f;
    #pragma unroll
    for (int k = 0; k < 5; ++k) {
        if ((lane >> k) & 1) {
            MM(q00,q01,q10,q11, P00[k],P01[k],P10[k],P11[k], q00,q01,q10,q11);
        }
    }

    float carry1 = 0.f, carry2 = 0.f;   // tile-in state (only tid 0's copy is used)

    const float4* __restrict__ xg4 = (const float4*)(x + (size_t)ch * TT);
    float4* __restrict__       yg4 = (float4*)(y + (size_t)ch * TT);
    float* const xc = xs + tid * LCH;

    for (int t = 0; t < NTILE; ++t) {
        // ---- stage tile: gmem -> smem, coalesced float4 ----
        const int base4 = t * (TILE / 4);
        #pragma unroll
        for (int i = tid; i < TILE / 4; i += NTHR)
            ((float4*)xs)[i] = __ldg(xg4 + base4 + i);
        __syncthreads();

        // ---- pass 1: run own chunk from zero state; write y_wrong in place ----
        float z1 = 0.f, z2 = 0.f;
        #pragma unroll
        for (int k = 0; k < LCH; ++k) {
            float v  = xc[k];
            float yn = fmaf(B0, v, z1);
            z1 = fmaf(B1, v, fmaf(nA1, yn, z2));
            z2 = fmaf(B2, v, nA2 * yn);
            xc[k] = yn;
        }

        // ---- warp-level inclusive affine scan of chunk end-states ----
        // E_l = sum_{j<=l} R^(l-j) e_j   (combine: E += R^(2^k) * E_{l-2^k})
        float E1 = z1, E2 = z2;
        #pragma unroll
        for (int k = 0; k < 5; ++k) {
            const int d = 1 << k;
            float u1 = __shfl_up_sync(0xffffffffu, E1, d);
            float u2 = __shfl_up_sync(0xffffffffu, E2, d);
            if (lane >= d) {
                E1 = fmaf(P00[k], u1, fmaf(P01[k], u2, E1));
                E2 = fmaf(P10[k], u1, fmaf(P11[k], u2, E2));
            }
        }
        if (lane == 31) { sT1[wrp] = E1; sT2[wrp] = E2; }
        __syncthreads();

        // ---- cross-warp serial combine (NW=10 entries, thread 0) ----
        if (tid == 0) {
            float c1 = carry1, c2 = carry2;
            #pragma unroll
            for (int w = 0; w < NW; ++w) {
                sC1[w] = c1; sC2[w] = c2;
                float n1 = fmaf(W00, c1, fmaf(W01, c2, sT1[w]));
                float n2 = fmaf(W10, c1, fmaf(W11, c2, sT2[w]));
                c1 = n1; c2 = n2;
            }
            carry1 = c1; carry2 = c2;   // tile-out state
        }
        __syncthreads();

        // ---- true start state of own chunk: S = R^lane * C_warp + E_exclusive ----
        float Ex1 = __shfl_up_sync(0xffffffffu, E1, 1);
        float Ex2 = __shfl_up_sync(0xffffffffu, E2, 1);
        if (lane == 0) { Ex1 = 0.f; Ex2 = 0.f; }
        float c1 = sC1[wrp], c2 = sC2[wrp];
        float d1 = q00 * c1 + q01 * c2 + Ex1;
        float d2 = q10 * c1 + q11 * c2 + Ex2;

        // ---- pass 2: homogeneous correction, y_true = y_wrong + delta_z1 ----
        // delta evolves as delta' = M delta (no input term)
        #pragma unroll
        for (int k = 0; k < LCH; ++k) {
            xc[k] = xc[k] + d1;
            float n1 = fmaf(nA1, d1, d2);
            d2 = nA2 * d1;
            d1 = n1;
        }
        __syncthreads();

        // ---- store tile: smem -> gmem, coalesced float4 ----
        #pragma unroll
        for (int i = tid; i < TILE / 4; i += NTHR)
            yg4[base4 + i] = ((float4*)xs)[i];
        __syncthreads();   // xs free for next tile's staging
    }
}

extern "C" void kernel_launch(void* const* d_in, const int* in_sizes, int n_in,
                              void* d_out, int out_size)
{
    const float* x  = (const float*)d_in[0];
    const float* b0 = (const float*)d_in[1];
    const float* b1 = (const float*)d_in[2];
    const float* b2 = (const float*)d_in[3];
    const float* a1 = (const float*)d_in[4];
    const float* a2 = (const float*)d_in[5];
    float* y = (float*)d_out;

    biquad_kernel<<<NCH, NTHR>>>(x, b0, b1, b2, a1, a2, y);
}